// round 5
// baseline (speedup 1.0000x reference)
#include <cuda_runtime.h>
#include <cstdint>

// Problem constants (fixed shapes)
#define T_STEPS 10
#define M_DIM   8
#define RD      256
#define D_INPUT 16
#define H_DIM   32
#define NMAT    9        // [B1, B2[0..7]]
#define BT      64       // batch tile per block
#define BTP     68       // padded smem stride for R tile (bank-conflict-free)
#define KC      16       // k-chunk staged in smem
#define NTH     512
#define NCHUNK  (NMAT * (RD / KC))   // 144 chunks per step

// Prescaled, transposed weights: g_Wpre[m][k][i] = rho * Bmat[i][k]
__device__ __align__(128) float g_Wpre[NMAT * RD * RD];

// ---------------- f32x2 packed helpers (FFMA2 path: 2x fp32 FMA rate) -------
__device__ __forceinline__ unsigned long long pk2(float lo, float hi) {
    unsigned long long r;
    asm("mov.b64 %0, {%1, %2};" : "=l"(r) : "f"(lo), "f"(hi));
    return r;
}
__device__ __forceinline__ void unpk2(unsigned long long v, float& lo, float& hi) {
    asm("mov.b64 {%0, %1}, %2;" : "=f"(lo), "=f"(hi) : "l"(v));
}
__device__ __forceinline__ unsigned long long ffma2(unsigned long long a,
                                                    unsigned long long b,
                                                    unsigned long long c) {
    unsigned long long d;
    asm("fma.rn.f32x2 %0, %1, %2, %3;" : "=l"(d) : "l"(a), "l"(b), "l"(c));
    return d;
}
__device__ __forceinline__ unsigned long long fadd2(unsigned long long a,
                                                    unsigned long long b) {
    unsigned long long d;
    asm("add.rn.f32x2 %0, %1, %2;" : "=l"(d) : "l"(a), "l"(b));
    return d;
}

// ---------------- prep: fold rho1/rho3 into transposed weight blob ----------
__global__ void prep_kernel(const float* __restrict__ B1m,
                            const float* __restrict__ B2m,
                            const float* __restrict__ rho1,
                            const float* __restrict__ rho3) {
    int idx = blockIdx.x * blockDim.x + threadIdx.x;
    if (idx >= NMAT * RD * RD) return;
    int m   = idx >> 16;       // / 65536
    int rem = idx & 65535;
    int k   = rem >> 8;
    int i   = rem & 255;
    float v = (m == 0) ? rho1[0] * B1m[i * RD + k]
                       : rho3[0] * B2m[((m - 1) * RD + i) * RD + k];
    g_Wpre[idx] = v;
}

// ---------------- per-timestep readout (all 512 threads) --------------------
__device__ __forceinline__ void do_readout(const float* __restrict__ Rt,
                                           const float* __restrict__ WroS,
                                           const float* __restrict__ broS,
                                           float* __restrict__ red,
                                           float* __restrict__ out,
                                           int bBase, int t, int tid) {
    int b = tid & 63, seg = tid >> 6;                 // 8 segments of 32 r's
    const float* wr = WroS + t * RD + seg * 32;
    const float* rp = Rt + (seg * 32) * BTP + b;
    float s = 0.f;
#pragma unroll
    for (int r = 0; r < 32; r++) s += rp[r * BTP] * wr[r];
    red[tid] = s;
    __syncthreads();
    if (tid < BT) {
        float a = broS[t];
#pragma unroll
        for (int q = 0; q < 8; q++) a += red[q * BT + tid];
        out[(size_t)(bBase + tid) * T_STEPS + t] = a;
    }
    __syncthreads();
}

// ---------------- main persistent kernel: one block per 64-batch tile -------
__global__ __launch_bounds__(NTH)
void sde_kernel(const float* __restrict__ V, const float* __restrict__ inc,
                const float* __restrict__ W1, const float* __restrict__ b1v,
                const float* __restrict__ W2, const float* __restrict__ b2v,
                const float* __restrict__ rho2, const float* __restrict__ rho4,
                const float* __restrict__ lam1, const float* __restrict__ lam2,
                const float* __restrict__ Wro,  const float* __restrict__ bro,
                float* __restrict__ out) {
    extern __shared__ float smem[];
    float* Rt    = smem;                    // [RD][BTP]  17408 floats
    float* Ach   = Rt + RD * BTP;           // [KC][RD]   4096
    float* biasS = Ach + KC * RD;           // [NMAT][RD] 2304
    float* WroS  = biasS + NMAT * RD;       // [T][RD]    2560
    float* broS  = WroS + T_STEPS * RD;     // 16
    float* dWs   = broS + 16;               // [M][BT]    512
    float* red   = dWs + M_DIM * BT;        // 512

    const int tid   = threadIdx.x;
    const int bBase = blockIdx.x * BT;
    const int lane  = tid & 31;
    const int warp  = tid >> 5;
    // thread tile: 8 rows x 4 cols of the (256 x 64) per-matrix output
    const int rowBase = (warp & 3) * 64 + (lane & 7) * 8;
    const int colBase = (warp >> 2) * 16 + (lane >> 3) * 4;

    // ---- prologue: biases (rho folded), readout weights ----
    {
        float r2 = rho2[0], r4 = rho4[0];
        for (int idx = tid; idx < NMAT * RD; idx += NTH) {
            int m = idx >> 8, i = idx & 255;
            biasS[idx] = (m == 0) ? r2 * lam1[i] : r4 * lam2[(m - 1) * RD + i];
        }
        for (int idx = tid; idx < T_STEPS * RD; idx += NTH) WroS[idx] = Wro[idx];
        if (tid < T_STEPS) broS[tid] = bro[tid];
    }

    // ---- h = tanh(V W1^T + b1) staged in Ach region ----
    float* hbuf = Ach;                       // 32*64 = 2048 <= 4096
    for (int idx = tid; idx < H_DIM * BT; idx += NTH) {
        int i = idx >> 6, b = idx & 63;
        const float* vb = V + (size_t)(bBase + b) * D_INPUT;
        const float* w  = W1 + i * D_INPUT;
        float s = b1v[i];
#pragma unroll
        for (int j = 0; j < D_INPUT; j++) s += vb[j] * w[j];
        hbuf[i * BT + b] = tanhf(s);
    }
    __syncthreads();

    // ---- R0 = h W2^T + b2 into Rt ----
    for (int idx = tid; idx < RD * BT; idx += NTH) {
        int r = idx >> 6, b = idx & 63;
        const float* w = W2 + r * H_DIM;
        float s = b2v[r];
#pragma unroll
        for (int j = 0; j < H_DIM; j++) s += hbuf[j * BT + b] * w[j];
        Rt[r * BTP + b] = s;
    }
    __syncthreads();

    do_readout(Rt, WroS, broS, red, out, bBase, 0, tid);

    const float4* wsrc = (const float4*)g_Wpre;

    // ---- 9 sequential SDE steps ----
    for (int s = 0; s < T_STEPS - 1; s++) {
        // dW for this step: dW[0] = inc0+inc1, dW[t>=1] = inc[t+1]
        {
            int m = tid >> 6, b = tid & 63;
            const float* incb = inc + (size_t)(bBase + b) * (T_STEPS * M_DIM);
            dWs[m * BT + b] = (s == 0) ? (incb[m] + incb[M_DIM + m])
                                       : incb[(s + 1) * M_DIM + m];
        }

        // Rn accumulator = R_prev  (packed f32x2 over column pairs)
        unsigned long long Rn[8][2];
#pragma unroll
        for (int r = 0; r < 8; r++) {
            float4 rv = *(const float4*)&Rt[(rowBase + r) * BTP + colBase];
            Rn[r][0] = pk2(rv.x, rv.y);
            Rn[r][1] = pk2(rv.z, rv.w);
        }

        // prime A prefetch (chunk 0)
        float4 p0 = wsrc[tid];
        float4 p1 = wsrc[512 + tid];

        for (int m = 0; m < NMAT; m++) {
            unsigned long long acc[8][2];
#pragma unroll
            for (int r = 0; r < 8; r++) { acc[r][0] = 0ULL; acc[r][1] = 0ULL; }

            for (int c = 0; c < RD / KC; c++) {
                __syncthreads();                       // Ach free (also covers dWs/Rt init on first iter)
                ((float4*)Ach)[tid]       = p0;
                ((float4*)Ach)[tid + 512] = p1;
                __syncthreads();
                int nc = m * (RD / KC) + c + 1;
                if (nc < NCHUNK) {                     // prefetch next chunk
                    p0 = wsrc[nc * 1024 + tid];
                    p1 = wsrc[nc * 1024 + 512 + tid];
                }
#pragma unroll
                for (int kk = 0; kk < KC; kk++) {
                    const float* ar = Ach + kk * RD + rowBase;
                    float4 a0 = *(const float4*)ar;
                    float4 a1 = *(const float4*)(ar + 4);
                    int gk = c * KC + kk;
                    float4 bv = *(const float4*)&Rt[gk * BTP + colBase];
                    unsigned long long bp0 = pk2(bv.x, bv.y);
                    unsigned long long bp1 = pk2(bv.z, bv.w);
                    float av[8] = {a0.x, a0.y, a0.z, a0.w, a1.x, a1.y, a1.z, a1.w};
#pragma unroll
                    for (int r = 0; r < 8; r++) {
                        unsigned long long ad = pk2(av[r], av[r]);
                        acc[r][0] = ffma2(ad, bp0, acc[r][0]);
                        acc[r][1] = ffma2(ad, bp1, acc[r][1]);
                    }
                }
            }

            // combine: Rn += tanh(acc + bias) [* dW for diffusion matrices]
            unsigned long long dw0 = 0ULL, dw1 = 0ULL;
            if (m > 0) {
                const float* dwp = dWs + (m - 1) * BT + colBase;
                dw0 = pk2(dwp[0], dwp[1]);
                dw1 = pk2(dwp[2], dwp[3]);
            }
#pragma unroll
            for (int r = 0; r < 8; r++) {
                float bias = biasS[m * RD + rowBase + r];
                float x0, x1, x2, x3;
                unpk2(acc[r][0], x0, x1);
                unpk2(acc[r][1], x2, x3);
                x0 = tanhf(x0 + bias); x1 = tanhf(x1 + bias);
                x2 = tanhf(x2 + bias); x3 = tanhf(x3 + bias);
                unsigned long long t0 = pk2(x0, x1), t1 = pk2(x2, x3);
                if (m == 0) {
                    Rn[r][0] = fadd2(Rn[r][0], t0);
                    Rn[r][1] = fadd2(Rn[r][1], t1);
                } else {
                    Rn[r][0] = ffma2(t0, dw0, Rn[r][0]);
                    Rn[r][1] = ffma2(t1, dw1, Rn[r][1]);
                }
            }
        }

        // write new state back to smem
        __syncthreads();                               // all Rt reads done
#pragma unroll
        for (int r = 0; r < 8; r++) {
            float x0, x1, x2, x3;
            unpk2(Rn[r][0], x0, x1);
            unpk2(Rn[r][1], x2, x3);
            *(float4*)&Rt[(rowBase + r) * BTP + colBase] = make_float4(x0, x1, x2, x3);
        }
        __syncthreads();

        do_readout(Rt, WroS, broS, red, out, bBase, s + 1, tid);
    }
}

// ---------------- launch ------------------------------------------------------
extern "C" void kernel_launch(void* const* d_in, const int* in_sizes, int n_in,
                              void* d_out, int out_size) {
    const float* V    = (const float*)d_in[0];
    const float* inc  = (const float*)d_in[1];
    const float* W1   = (const float*)d_in[2];
    const float* b1v  = (const float*)d_in[3];
    const float* W2   = (const float*)d_in[4];
    const float* b2v  = (const float*)d_in[5];
    const float* rho1 = (const float*)d_in[6];
    const float* rho2 = (const float*)d_in[7];
    const float* rho3 = (const float*)d_in[8];
    const float* rho4 = (const float*)d_in[9];
    const float* B1m  = (const float*)d_in[10];
    const float* B2m  = (const float*)d_in[11];
    const float* lam1 = (const float*)d_in[12];
    const float* lam2 = (const float*)d_in[13];
    const float* Wro  = (const float*)d_in[14];
    const float* bro  = (const float*)d_in[15];
    float* out = (float*)d_out;

    const int nB = in_sizes[0] / D_INPUT;          // 16384

    // 1) prescale + transpose weights into device scratch
    prep_kernel<<<(NMAT * RD * RD + 255) / 256, 256>>>(B1m, B2m, rho1, rho3);

    // 2) persistent SDE kernel, one block per 64-batch tile
    const int smemFloats = RD * BTP + KC * RD + NMAT * RD + T_STEPS * RD + 16
                         + M_DIM * BT + NTH;
    const size_t smemBytes = (size_t)smemFloats * sizeof(float);
    cudaFuncSetAttribute(sde_kernel, cudaFuncAttributeMaxDynamicSharedMemorySize,
                         (int)smemBytes);
    sde_kernel<<<nB / BT, NTH, smemBytes>>>(V, inc, W1, b1v, W2, b2v,
                                            rho2, rho4, lam1, lam2, Wro, bro, out);
}

// round 7
// speedup vs baseline: 1.3455x; 1.3455x over previous
#include <cuda_runtime.h>
#include <cstdint>

// Fixed problem shapes
#define T_STEPS 10
#define M_DIM   8
#define RD      256
#define D_INPUT 16
#define H_DIM   32
#define NMAT    9          // [B1, B2[0..7]]
#define BT      64         // batch tile per block
#define RSTR    136        // duplicated-R smem row stride (2*BT + 8 pad)
#define KC      16         // k-chunk staged in smem
#define NTH     512
#define KCRD    (KC * RD)
#define NCHUNK  (NMAT * (RD / KC))   // 144 chunks per step

// Prescaled, transposed weights: g_Wpre[m][k][i] = rho * Bmat[i][k]
__device__ __align__(128) float g_Wpre[NMAT * RD * RD];

typedef unsigned long long u64;

// ---------------- f32x2 packed helpers (FFMA2: 2x fp32 FMA rate) ------------
__device__ __forceinline__ u64 pk2(float lo, float hi) {
    u64 r; asm("mov.b64 %0, {%1, %2};" : "=l"(r) : "f"(lo), "f"(hi)); return r;
}
__device__ __forceinline__ void unpk2(u64 v, float& lo, float& hi) {
    asm("mov.b64 {%0, %1}, %2;" : "=f"(lo), "=f"(hi) : "l"(v));
}
__device__ __forceinline__ u64 ffma2(u64 a, u64 b, u64 c) {
    u64 d; asm("fma.rn.f32x2 %0, %1, %2, %3;" : "=l"(d) : "l"(a), "l"(b), "l"(c));
    return d;
}
__device__ __forceinline__ u64 fadd2(u64 a, u64 b) {
    u64 d; asm("add.rn.f32x2 %0, %1, %2;" : "=l"(d) : "l"(a), "l"(b)); return d;
}

// ---------------- prep: fold rho1/rho3 into transposed weight blob ----------
__global__ void prep_kernel(const float* __restrict__ B1m,
                            const float* __restrict__ B2m,
                            const float* __restrict__ rho1,
                            const float* __restrict__ rho3) {
    int idx = blockIdx.x * blockDim.x + threadIdx.x;
    if (idx >= NMAT * RD * RD) return;
    int m   = idx >> 16;
    int rem = idx & 65535;
    int k   = rem >> 8;
    int i   = rem & 255;
    float v = (m == 0) ? rho1[0] * B1m[i * RD + k]
                       : rho3[0] * B2m[((m - 1) * RD + i) * RD + k];
    g_Wpre[idx] = v;
}

// ---------------- per-timestep readout (all 512 threads) --------------------
__device__ __forceinline__ void do_readout(const float* __restrict__ Rtd,
                                           const float* __restrict__ WroS,
                                           const float* __restrict__ broS,
                                           float* __restrict__ red,
                                           float* __restrict__ out,
                                           int bBase, int t, int tid) {
    int b = tid & 63, seg = tid >> 6;                 // 8 segments of 32 r's
    const float* wr = WroS + t * RD + seg * 32;
    const float* rp = Rtd + (seg * 32) * RSTR + 2 * b;
    float s = 0.f;
#pragma unroll
    for (int r = 0; r < 32; r++) s += rp[r * RSTR] * wr[r];
    red[tid] = s;
    __syncthreads();
    if (tid < BT) {
        float a = broS[t];
#pragma unroll
        for (int q = 0; q < 8; q++) a += red[q * BT + tid];
        out[(size_t)(bBase + tid) * T_STEPS + t] = a;
    }
    __syncthreads();
}

// ---------------- main kernel: one block per 64-batch tile ------------------
__global__ __launch_bounds__(NTH, 1)
void sde_kernel(const float* __restrict__ V, const float* __restrict__ inc,
                const float* __restrict__ W1, const float* __restrict__ b1v,
                const float* __restrict__ W2, const float* __restrict__ b2v,
                const float* __restrict__ rho2, const float* __restrict__ rho4,
                const float* __restrict__ lam1, const float* __restrict__ lam2,
                const float* __restrict__ Wro,  const float* __restrict__ bro,
                float* __restrict__ out) {
    extern __shared__ float smem[];
    float* Rtd   = smem;                    // [RD][RSTR] duplicated R  34816
    float* Abuf  = Rtd + RD * RSTR;         // 2 x [KC][RD] ping-pong   8192
    float* biasS = Abuf + 2 * KCRD;         // [NMAT][RD]               2304
    float* WroS  = biasS + NMAT * RD;       // [T][RD]                  2560
    float* broS  = WroS + T_STEPS * RD;     // 16
    float* dWs   = broS + 16;               // [M][BT]                  512
    float* red   = dWs + M_DIM * BT;        // 512

    const int tid   = threadIdx.x;
    const int bBase = blockIdx.x * BT;
    const int lane  = tid & 31;
    const int warp  = tid >> 5;
    // thread tile: rows rb..rb+3 and rb+32..rb+35 (8 rows), 4 cols.
    // Warp A-addresses: 8 groups at 16B stride -> all 32 banks, conflict-free.
    const int rb      = (warp & 3) * 64 + (lane >> 2) * 4;
    const int colBase = (warp >> 2) * 16 + (lane & 3) * 4;
    // row-pair bases for the 4 f32x2 accum row-pairs
    const int rowOf0 = rb, rowOf1 = rb + 2, rowOf2 = rb + 32, rowOf3 = rb + 34;
    const int rowOf[4] = {rowOf0, rowOf1, rowOf2, rowOf3};

    // ---- prologue: biases (rho folded), readout weights ----
    {
        float r2 = rho2[0], r4 = rho4[0];
        for (int idx = tid; idx < NMAT * RD; idx += NTH) {
            int m = idx >> 8, i = idx & 255;
            biasS[idx] = (m == 0) ? r2 * lam1[i] : r4 * lam2[(m - 1) * RD + i];
        }
        for (int idx = tid; idx < T_STEPS * RD; idx += NTH) WroS[idx] = Wro[idx];
        if (tid < T_STEPS) broS[tid] = bro[tid];
    }

    // ---- h = tanh(V W1^T + b1), staged in Abuf region ----
    float* hbuf = Abuf;                      // 32*64 = 2048 <= 8192
    for (int idx = tid; idx < H_DIM * BT; idx += NTH) {
        int i = idx >> 6, b = idx & 63;
        const float* vb = V + (size_t)(bBase + b) * D_INPUT;
        const float* w  = W1 + i * D_INPUT;
        float s = b1v[i];
#pragma unroll
        for (int j = 0; j < D_INPUT; j++) s += vb[j] * w[j];
        hbuf[i * BT + b] = tanhf(s);
    }
    __syncthreads();

    // ---- R0 = h W2^T + b2 -> Rtd (duplicated) ----
    for (int idx = tid; idx < RD * BT; idx += NTH) {
        int r = idx >> 6, b = idx & 63;
        const float* w = W2 + r * H_DIM;
        float s = b2v[r];
#pragma unroll
        for (int j = 0; j < H_DIM; j++) s += hbuf[j * BT + b] * w[j];
        float* q = Rtd + r * RSTR + 2 * b;
        q[0] = s; q[1] = s;
    }
    __syncthreads();

    do_readout(Rtd, WroS, broS, red, out, bBase, 0, tid);

    const float4* wsrc = (const float4*)g_Wpre;

    // ---- 9 sequential SDE steps ----
    for (int s = 0; s < T_STEPS - 1; s++) {
        // dW for this step
        {
            int m = tid >> 6, b = tid & 63;
            const float* incb = inc + (size_t)(bBase + b) * (T_STEPS * M_DIM);
            dWs[m * BT + b] = (s == 0) ? (incb[m] + incb[M_DIM + m])
                                       : incb[(s + 1) * M_DIM + m];
        }

        // Rn = R_prev (row-paired f32x2 regs)
        u64 Rn[4][4];
#pragma unroll
        for (int rp = 0; rp < 4; rp++)
#pragma unroll
            for (int c = 0; c < 4; c++) {
                const float* q = Rtd + rowOf[rp] * RSTR + 2 * (colBase + c);
                Rn[rp][c] = pk2(q[0], q[RSTR]);
            }

        // prime ping-pong: buf0 <- chunk0, prefetch chunk1 (plain layout)
        float4 p0 = wsrc[tid], p1 = wsrc[512 + tid];
        ((float4*)Abuf)[tid]       = p0;
        ((float4*)Abuf)[tid + 512] = p1;
        p0 = wsrc[1024 + tid]; p1 = wsrc[1536 + tid];
        __syncthreads();                       // buf0 ready

        for (int m = 0; m < NMAT; m++) {
            u64 acc[4][4];
#pragma unroll
            for (int rp = 0; rp < 4; rp++)
#pragma unroll
                for (int c = 0; c < 4; c++) acc[rp][c] = 0ULL;

            for (int c16 = 0; c16 < RD / KC; c16++) {
                const int ch = m * (RD / KC) + c16;

                // overlap: store chunk ch+1 into the idle buffer, prefetch ch+2
                if (ch + 1 < NCHUNK) {
                    float4* dst = (float4*)(Abuf + ((ch + 1) & 1) * KCRD);
                    dst[tid]       = p0;
                    dst[tid + 512] = p1;
                }
                if (ch + 2 < NCHUNK) {
                    p0 = wsrc[(ch + 2) * 1024 + tid];
                    p1 = wsrc[(ch + 2) * 1024 + 512 + tid];
                }

                const float* Ac = Abuf + (ch & 1) * KCRD;
                const float* Bb = Rtd + (c16 * KC) * RSTR + 2 * colBase;
#pragma unroll
                for (int kk = 0; kk < KC; kk++) {
                    ulonglong2 aa0 = *(const ulonglong2*)(Ac + kk * RD + rb);
                    ulonglong2 aa1 = *(const ulonglong2*)(Ac + kk * RD + rb + 32);
                    ulonglong2 bb0 = *(const ulonglong2*)(Bb + kk * RSTR);
                    ulonglong2 bb1 = *(const ulonglong2*)(Bb + kk * RSTR + 4);
                    u64 au[4] = {aa0.x, aa0.y, aa1.x, aa1.y};
                    u64 bu[4] = {bb0.x, bb0.y, bb1.x, bb1.y};
#pragma unroll
                    for (int rp = 0; rp < 4; rp++)
#pragma unroll
                        for (int c = 0; c < 4; c++)
                            acc[rp][c] = ffma2(au[rp], bu[c], acc[rp][c]);
                }
                __syncthreads();               // next buffer ready / this one free
            }

            // combine: Rn += tanh(acc + bias) [* dW for diffusion matrices]
            u64 dwd[4];
            if (m > 0) {
#pragma unroll
                for (int c = 0; c < 4; c++) {
                    float d = dWs[(m - 1) * BT + colBase + c];
                    dwd[c] = pk2(d, d);
                }
            }
#pragma unroll
            for (int rp = 0; rp < 4; rp++) {
                float bA = biasS[m * RD + rowOf[rp]];
                float bB = biasS[m * RD + rowOf[rp] + 1];
#pragma unroll
                for (int c = 0; c < 4; c++) {
                    float x0, x1;
                    unpk2(acc[rp][c], x0, x1);
                    x0 = tanhf(x0 + bA);
                    x1 = tanhf(x1 + bB);
                    u64 t = pk2(x0, x1);
                    Rn[rp][c] = (m == 0) ? fadd2(Rn[rp][c], t)
                                         : ffma2(t, dwd[c], Rn[rp][c]);
                }
            }
        }

        // write new state (duplicated); last chunk's barrier already passed
#pragma unroll
        for (int rp = 0; rp < 4; rp++) {
            float x0[4], x1[4];
#pragma unroll
            for (int c = 0; c < 4; c++) unpk2(Rn[rp][c], x0[c], x1[c]);
            float* qa = Rtd + rowOf[rp] * RSTR + 2 * colBase;
            *(float4*)qa       = make_float4(x0[0], x0[0], x0[1], x0[1]);
            *(float4*)(qa + 4) = make_float4(x0[2], x0[2], x0[3], x0[3]);
            float* qb = qa + RSTR;
            *(float4*)qb       = make_float4(x1[0], x1[0], x1[1], x1[1]);
            *(float4*)(qb + 4) = make_float4(x1[2], x1[2], x1[3], x1[3]);
        }
        __syncthreads();

        do_readout(Rtd, WroS, broS, red, out, bBase, s + 1, tid);
    }
}

// ---------------- launch -----------------------------------------------------
extern "C" void kernel_launch(void* const* d_in, const int* in_sizes, int n_in,
                              void* d_out, int out_size) {
    const float* V    = (const float*)d_in[0];
    const float* inc  = (const float*)d_in[1];
    const float* W1   = (const float*)d_in[2];
    const float* b1v  = (const float*)d_in[3];
    const float* W2   = (const float*)d_in[4];
    const float* b2v  = (const float*)d_in[5];
    const float* rho1 = (const float*)d_in[6];
    const float* rho2 = (const float*)d_in[7];
    const float* rho3 = (const float*)d_in[8];
    const float* rho4 = (const float*)d_in[9];
    const float* B1m  = (const float*)d_in[10];
    const float* B2m  = (const float*)d_in[11];
    const float* lam1 = (const float*)d_in[12];
    const float* lam2 = (const float*)d_in[13];
    const float* Wro  = (const float*)d_in[14];
    const float* bro  = (const float*)d_in[15];
    float* out = (float*)d_out;

    const int nB = in_sizes[0] / D_INPUT;          // 16384

    prep_kernel<<<(NMAT * RD * RD + 255) / 256, 256>>>(B1m, B2m, rho1, rho3);

    const int smemFloats = RD * RSTR + 2 * KCRD + NMAT * RD + T_STEPS * RD + 16
                         + M_DIM * BT + NTH;
    const size_t smemBytes = (size_t)smemFloats * sizeof(float);
    cudaFuncSetAttribute(sde_kernel, cudaFuncAttributeMaxDynamicSharedMemorySize,
                         (int)smemBytes);
    sde_kernel<<<nB / BT, NTH, smemBytes>>>(V, inc, W1, b1v, W2, b2v,
                                            rho2, rho4, lam1, lam2, Wro, bro, out);
}

// round 8
// speedup vs baseline: 1.3456x; 1.0000x over previous
#include <cuda_runtime.h>
#include <cstdint>

// Fixed problem shapes
#define T_STEPS 10
#define M_DIM   8
#define RD      256
#define D_INPUT 16
#define H_DIM   32
#define NMAT    9          // [B1, B2[0..7]]
#define BT      64         // batch tile per block
#define RSTR    136        // duplicated-R smem row stride (2*BT + 8 pad)
#define KC      16         // k-chunk staged in smem
#define NTH     512
#define KCRD    (KC * RD)
#define NCHUNK  (NMAT * (RD / KC))   // 144 chunks per step

// Prescaled, transposed weights: g_Wpre[m][k][i] = rho * Bmat[i][k]
__device__ __align__(128) float g_Wpre[NMAT * RD * RD];

typedef unsigned long long u64;

// ---------------- f32x2 packed helpers (FFMA2: 2x fp32 FMA rate) ------------
__device__ __forceinline__ u64 pk2(float lo, float hi) {
    u64 r; asm("mov.b64 %0, {%1, %2};" : "=l"(r) : "f"(lo), "f"(hi)); return r;
}
__device__ __forceinline__ void unpk2(u64 v, float& lo, float& hi) {
    asm("mov.b64 {%0, %1}, %2;" : "=f"(lo), "=f"(hi) : "l"(v));
}
__device__ __forceinline__ u64 ffma2(u64 a, u64 b, u64 c) {
    u64 d; asm("fma.rn.f32x2 %0, %1, %2, %3;" : "=l"(d) : "l"(a), "l"(b), "l"(c));
    return d;
}
__device__ __forceinline__ u64 fadd2(u64 a, u64 b) {
    u64 d; asm("add.rn.f32x2 %0, %1, %2;" : "=l"(d) : "l"(a), "l"(b)); return d;
}

// ---------------- prep: fold rho1/rho3 into transposed weight blob ----------
__global__ void prep_kernel(const float* __restrict__ B1m,
                            const float* __restrict__ B2m,
                            const float* __restrict__ rho1,
                            const float* __restrict__ rho3) {
    int idx = blockIdx.x * blockDim.x + threadIdx.x;
    if (idx >= NMAT * RD * RD) return;
    int m   = idx >> 16;
    int rem = idx & 65535;
    int k   = rem >> 8;
    int i   = rem & 255;
    float v = (m == 0) ? rho1[0] * B1m[i * RD + k]
                       : rho3[0] * B2m[((m - 1) * RD + i) * RD + k];
    g_Wpre[idx] = v;
}

// ---------------- per-timestep readout (all 512 threads) --------------------
__device__ __forceinline__ void do_readout(const float* __restrict__ Rtd,
                                           const float* __restrict__ WroS,
                                           const float* __restrict__ broS,
                                           float* __restrict__ red,
                                           float* __restrict__ out,
                                           int bBase, int t, int tid) {
    int b = tid & 63, seg = tid >> 6;                 // 8 segments of 32 r's
    const float* wr = WroS + t * RD + seg * 32;
    const float* rp = Rtd + (seg * 32) * RSTR + 2 * b;
    float s = 0.f;
#pragma unroll
    for (int r = 0; r < 32; r++) s += rp[r * RSTR] * wr[r];
    red[tid] = s;
    __syncthreads();
    if (tid < BT) {
        float a = broS[t];
#pragma unroll
        for (int q = 0; q < 8; q++) a += red[q * BT + tid];
        out[(size_t)(bBase + tid) * T_STEPS + t] = a;
    }
    __syncthreads();
}

// ---------------- main kernel: one block per 64-batch tile ------------------
__global__ __launch_bounds__(NTH, 1)
void sde_kernel(const float* __restrict__ V, const float* __restrict__ inc,
                const float* __restrict__ W1, const float* __restrict__ b1v,
                const float* __restrict__ W2, const float* __restrict__ b2v,
                const float* __restrict__ rho2, const float* __restrict__ rho4,
                const float* __restrict__ lam1, const float* __restrict__ lam2,
                const float* __restrict__ Wro,  const float* __restrict__ bro,
                float* __restrict__ out) {
    extern __shared__ float smem[];
    float* Rtd   = smem;                    // [RD][RSTR] duplicated R  34816
    float* Abuf  = Rtd + RD * RSTR;         // 2 x [KC][RD] ping-pong   8192
    float* biasS = Abuf + 2 * KCRD;         // [NMAT][RD]               2304
    float* WroS  = biasS + NMAT * RD;       // [T][RD]                  2560
    float* broS  = WroS + T_STEPS * RD;     // 16
    float* dWs   = broS + 16;               // [M][BT]                  512
    float* red   = dWs + M_DIM * BT;        // 512

    const int tid   = threadIdx.x;
    const int bBase = blockIdx.x * BT;
    const int lane  = tid & 31;
    const int warp  = tid >> 5;
    // thread tile: rows rb..rb+3 and rb+32..rb+35 (8 rows), 4 cols.
    // Warp A-addresses: 8 groups at 16B stride -> all 32 banks, conflict-free.
    const int rb      = (warp & 3) * 64 + (lane >> 2) * 4;
    const int colBase = (warp >> 2) * 16 + (lane & 3) * 4;
    // row-pair bases for the 4 f32x2 accum row-pairs
    const int rowOf0 = rb, rowOf1 = rb + 2, rowOf2 = rb + 32, rowOf3 = rb + 34;
    const int rowOf[4] = {rowOf0, rowOf1, rowOf2, rowOf3};

    // ---- prologue: biases (rho folded), readout weights ----
    {
        float r2 = rho2[0], r4 = rho4[0];
        for (int idx = tid; idx < NMAT * RD; idx += NTH) {
            int m = idx >> 8, i = idx & 255;
            biasS[idx] = (m == 0) ? r2 * lam1[i] : r4 * lam2[(m - 1) * RD + i];
        }
        for (int idx = tid; idx < T_STEPS * RD; idx += NTH) WroS[idx] = Wro[idx];
        if (tid < T_STEPS) broS[tid] = bro[tid];
    }

    // ---- h = tanh(V W1^T + b1), staged in Abuf region ----
    float* hbuf = Abuf;                      // 32*64 = 2048 <= 8192
    for (int idx = tid; idx < H_DIM * BT; idx += NTH) {
        int i = idx >> 6, b = idx & 63;
        const float* vb = V + (size_t)(bBase + b) * D_INPUT;
        const float* w  = W1 + i * D_INPUT;
        float s = b1v[i];
#pragma unroll
        for (int j = 0; j < D_INPUT; j++) s += vb[j] * w[j];
        hbuf[i * BT + b] = tanhf(s);
    }
    __syncthreads();

    // ---- R0 = h W2^T + b2 -> Rtd (duplicated) ----
    for (int idx = tid; idx < RD * BT; idx += NTH) {
        int r = idx >> 6, b = idx & 63;
        const float* w = W2 + r * H_DIM;
        float s = b2v[r];
#pragma unroll
        for (int j = 0; j < H_DIM; j++) s += hbuf[j * BT + b] * w[j];
        float* q = Rtd + r * RSTR + 2 * b;
        q[0] = s; q[1] = s;
    }
    __syncthreads();

    do_readout(Rtd, WroS, broS, red, out, bBase, 0, tid);

    const float4* wsrc = (const float4*)g_Wpre;

    // ---- 9 sequential SDE steps ----
    for (int s = 0; s < T_STEPS - 1; s++) {
        // dW for this step
        {
            int m = tid >> 6, b = tid & 63;
            const float* incb = inc + (size_t)(bBase + b) * (T_STEPS * M_DIM);
            dWs[m * BT + b] = (s == 0) ? (incb[m] + incb[M_DIM + m])
                                       : incb[(s + 1) * M_DIM + m];
        }

        // Rn = R_prev (row-paired f32x2 regs)
        u64 Rn[4][4];
#pragma unroll
        for (int rp = 0; rp < 4; rp++)
#pragma unroll
            for (int c = 0; c < 4; c++) {
                const float* q = Rtd + rowOf[rp] * RSTR + 2 * (colBase + c);
                Rn[rp][c] = pk2(q[0], q[RSTR]);
            }

        // prime ping-pong: buf0 <- chunk0, prefetch chunk1 (plain layout)
        float4 p0 = wsrc[tid], p1 = wsrc[512 + tid];
        ((float4*)Abuf)[tid]       = p0;
        ((float4*)Abuf)[tid + 512] = p1;
        p0 = wsrc[1024 + tid]; p1 = wsrc[1536 + tid];
        __syncthreads();                       // buf0 ready

        for (int m = 0; m < NMAT; m++) {
            u64 acc[4][4];
#pragma unroll
            for (int rp = 0; rp < 4; rp++)
#pragma unroll
                for (int c = 0; c < 4; c++) acc[rp][c] = 0ULL;

            for (int c16 = 0; c16 < RD / KC; c16++) {
                const int ch = m * (RD / KC) + c16;

                // overlap: store chunk ch+1 into the idle buffer, prefetch ch+2
                if (ch + 1 < NCHUNK) {
                    float4* dst = (float4*)(Abuf + ((ch + 1) & 1) * KCRD);
                    dst[tid]       = p0;
                    dst[tid + 512] = p1;
                }
                if (ch + 2 < NCHUNK) {
                    p0 = wsrc[(ch + 2) * 1024 + tid];
                    p1 = wsrc[(ch + 2) * 1024 + 512 + tid];
                }

                const float* Ac = Abuf + (ch & 1) * KCRD;
                const float* Bb = Rtd + (c16 * KC) * RSTR + 2 * colBase;
#pragma unroll
                for (int kk = 0; kk < KC; kk++) {
                    ulonglong2 aa0 = *(const ulonglong2*)(Ac + kk * RD + rb);
                    ulonglong2 aa1 = *(const ulonglong2*)(Ac + kk * RD + rb + 32);
                    ulonglong2 bb0 = *(const ulonglong2*)(Bb + kk * RSTR);
                    ulonglong2 bb1 = *(const ulonglong2*)(Bb + kk * RSTR + 4);
                    u64 au[4] = {aa0.x, aa0.y, aa1.x, aa1.y};
                    u64 bu[4] = {bb0.x, bb0.y, bb1.x, bb1.y};
#pragma unroll
                    for (int rp = 0; rp < 4; rp++)
#pragma unroll
                        for (int c = 0; c < 4; c++)
                            acc[rp][c] = ffma2(au[rp], bu[c], acc[rp][c]);
                }
                __syncthreads();               // next buffer ready / this one free
            }

            // combine: Rn += tanh(acc + bias) [* dW for diffusion matrices]
            u64 dwd[4];
            if (m > 0) {
#pragma unroll
                for (int c = 0; c < 4; c++) {
                    float d = dWs[(m - 1) * BT + colBase + c];
                    dwd[c] = pk2(d, d);
                }
            }
#pragma unroll
            for (int rp = 0; rp < 4; rp++) {
                float bA = biasS[m * RD + rowOf[rp]];
                float bB = biasS[m * RD + rowOf[rp] + 1];
#pragma unroll
                for (int c = 0; c < 4; c++) {
                    float x0, x1;
                    unpk2(acc[rp][c], x0, x1);
                    x0 = tanhf(x0 + bA);
                    x1 = tanhf(x1 + bB);
                    u64 t = pk2(x0, x1);
                    Rn[rp][c] = (m == 0) ? fadd2(Rn[rp][c], t)
                                         : ffma2(t, dwd[c], Rn[rp][c]);
                }
            }
        }

        // write new state (duplicated); last chunk's barrier already passed
#pragma unroll
        for (int rp = 0; rp < 4; rp++) {
            float x0[4], x1[4];
#pragma unroll
            for (int c = 0; c < 4; c++) unpk2(Rn[rp][c], x0[c], x1[c]);
            float* qa = Rtd + rowOf[rp] * RSTR + 2 * colBase;
            *(float4*)qa       = make_float4(x0[0], x0[0], x0[1], x0[1]);
            *(float4*)(qa + 4) = make_float4(x0[2], x0[2], x0[3], x0[3]);
            float* qb = qa + RSTR;
            *(float4*)qb       = make_float4(x1[0], x1[0], x1[1], x1[1]);
            *(float4*)(qb + 4) = make_float4(x1[2], x1[2], x1[3], x1[3]);
        }
        __syncthreads();

        do_readout(Rtd, WroS, broS, red, out, bBase, s + 1, tid);
    }
}

// ---------------- launch -----------------------------------------------------
extern "C" void kernel_launch(void* const* d_in, const int* in_sizes, int n_in,
                              void* d_out, int out_size) {
    const float* V    = (const float*)d_in[0];
    const float* inc  = (const float*)d_in[1];
    const float* W1   = (const float*)d_in[2];
    const float* b1v  = (const float*)d_in[3];
    const float* W2   = (const float*)d_in[4];
    const float* b2v  = (const float*)d_in[5];
    const float* rho1 = (const float*)d_in[6];
    const float* rho2 = (const float*)d_in[7];
    const float* rho3 = (const float*)d_in[8];
    const float* rho4 = (const float*)d_in[9];
    const float* B1m  = (const float*)d_in[10];
    const float* B2m  = (const float*)d_in[11];
    const float* lam1 = (const float*)d_in[12];
    const float* lam2 = (const float*)d_in[13];
    const float* Wro  = (const float*)d_in[14];
    const float* bro  = (const float*)d_in[15];
    float* out = (float*)d_out;

    const int nB = in_sizes[0] / D_INPUT;          // 16384

    prep_kernel<<<(NMAT * RD * RD + 255) / 256, 256>>>(B1m, B2m, rho1, rho3);

    const int smemFloats = RD * RSTR + 2 * KCRD + NMAT * RD + T_STEPS * RD + 16
                         + M_DIM * BT + NTH;
    const size_t smemBytes = (size_t)smemFloats * sizeof(float);
    cudaFuncSetAttribute(sde_kernel, cudaFuncAttributeMaxDynamicSharedMemorySize,
                         (int)smemBytes);
    sde_kernel<<<nB / BT, NTH, smemBytes>>>(V, inc, W1, b1v, W2, b2v,
                                            rho2, rho4, lam1, lam2, Wro, bro, out);
}

// round 10
// speedup vs baseline: 2.8881x; 2.1463x over previous
#include <cuda_runtime.h>
#include <cuda_bf16.h>
#include <cstdint>
typedef unsigned int u32;

#define NTH  512
#define BT   64
#define RSTR 72
// smem byte offsets
#define SO_R    0          // fp32 R state [256][72]         73728
#define SO_BH   73728      // B hi frags [16q][8nt][32l][2]   32768
#define SO_BL   106496     // B lo frags                      32768
#define SO_AB   139264     // A ping-pong 2 x 16KB            32768
#define SO_BIAS 172032     // 9*256 fp32                       9216
#define SO_WRO  181248     // 10*256 fp32                     10240
#define SO_BRO  191488     // 10 fp32 (pad)                      64
#define SO_DW   191552     // 8*64 fp32                        2048
#define SO_RED  193600     // 512 fp32                         2048
#define SM_TOT  195648

// A fragments: [chunk 0..143][split 2][mtile 16][lane 32][4 u32]
__device__ __align__(256) u32 g_A[144 * 4096];

__device__ __forceinline__ u32 pkbf(__nv_bfloat16 a, __nv_bfloat16 b) {
    return (u32)__bfloat16_as_ushort(a) | ((u32)__bfloat16_as_ushort(b) << 16);
}
__device__ __forceinline__ void mma16816(float c[4], const uint4& a, const uint2& b) {
    asm volatile("mma.sync.aligned.m16n8k16.row.col.f32.bf16.bf16.f32 "
        "{%0,%1,%2,%3}, {%4,%5,%6,%7}, {%8,%9}, {%0,%1,%2,%3};"
        : "+f"(c[0]), "+f"(c[1]), "+f"(c[2]), "+f"(c[3])
        : "r"(a.x), "r"(a.y), "r"(a.z), "r"(a.w), "r"(b.x), "r"(b.y));
}

// ---------------- prep: rho-fold + bf16 hi/lo split + fragment layout -------
__global__ void prep_kernel(const float* __restrict__ B1m, const float* __restrict__ B2m,
                            const float* __restrict__ r1, const float* __restrict__ r3) {
    int idx = blockIdx.x * 256 + threadIdx.x;
    if (idx >= 144 * 16 * 32 * 4) return;
    int r = idx & 3, l = (idx >> 2) & 31, mt = (idx >> 7) & 15, ch = idx >> 11;
    int m = ch >> 4, q = ch & 15;
    int gg = l >> 2, tt = l & 3;
    int i = mt * 16 + gg + ((r & 1) ? 8 : 0);
    int k = q * 16 + 2 * tt + ((r & 2) ? 8 : 0);
    float rho = (m == 0) ? r1[0] : r3[0];
    const float* Bs = (m == 0) ? (B1m + i * 256) : (B2m + (m - 1) * 65536 + i * 256);
    float v0 = rho * Bs[k], v1 = rho * Bs[k + 1];
    __nv_bfloat16 h0 = __float2bfloat16(v0), h1 = __float2bfloat16(v1);
    __nv_bfloat16 e0 = __float2bfloat16(v0 - __bfloat162float(h0));
    __nv_bfloat16 e1 = __float2bfloat16(v1 - __bfloat162float(h1));
    int base = ch * 4096 + mt * 128 + l * 4 + r;
    g_A[base]        = pkbf(h0, h1);
    g_A[base + 2048] = pkbf(e0, e1);
}

// ---------------- main kernel ------------------------------------------------
__global__ __launch_bounds__(NTH, 1)
void sde_kernel(const float* __restrict__ V, const float* __restrict__ inc,
                const float* __restrict__ W1, const float* __restrict__ b1v,
                const float* __restrict__ W2, const float* __restrict__ b2v,
                const float* __restrict__ rho2, const float* __restrict__ rho4,
                const float* __restrict__ lam1, const float* __restrict__ lam2,
                const float* __restrict__ Wro,  const float* __restrict__ bro,
                float* __restrict__ out) {
    extern __shared__ __align__(16) char sm[];
    float* R     = (float*)(sm + SO_R);
    u32*   BH    = (u32*)(sm + SO_BH);
    u32*   BL    = (u32*)(sm + SO_BL);
    u32*   AB    = (u32*)(sm + SO_AB);
    float* biasS = (float*)(sm + SO_BIAS);
    float* WroS  = (float*)(sm + SO_WRO);
    float* broS  = (float*)(sm + SO_BRO);
    float* dWs   = (float*)(sm + SO_DW);
    float* red   = (float*)(sm + SO_RED);

    const int tid = threadIdx.x, lane = tid & 31, w = tid >> 5;
    const int g = lane >> 2, t = lane & 3;
    const int rb = (w & 3) * 64, cbw = (w >> 2) * 16;
    const int bBase = blockIdx.x * BT;

    // prologue: biases (rho folded), readout weights
    {
        float r2 = rho2[0], r4 = rho4[0];
        for (int e = tid; e < 2304; e += NTH) {
            int m = e >> 8, i = e & 255;
            biasS[e] = (m == 0) ? r2 * lam1[i] : r4 * lam2[(m - 1) * 256 + i];
        }
        for (int e = tid; e < 2560; e += NTH) WroS[e] = Wro[e];
        if (tid < 10) broS[tid] = bro[tid];
    }
    // h = tanh(V W1^T + b1), staged in AB scratch
    float* hb = (float*)AB;
    for (int e = tid; e < 2048; e += NTH) {
        int b = e >> 5, j = e & 31;
        const float* vb = V + (size_t)(bBase + b) * 16;
        const float* ww = W1 + j * 16;
        float s = b1v[j];
#pragma unroll
        for (int u2 = 0; u2 < 16; u2++) s += vb[u2] * ww[u2];
        hb[b * 32 + j] = tanhf(s);
    }
    __syncthreads();
    // R0 = h W2^T + b2
    for (int e = tid; e < 16384; e += NTH) {
        int i = e >> 6, b = e & 63;
        const float* ww = W2 + i * 32;
        const float* hr = hb + b * 32;
        float s = b2v[i];
#pragma unroll
        for (int j = 0; j < 32; j++) s += hr[j] * ww[j];
        R[i * RSTR + b] = s;
    }
    __syncthreads();

    // rebuild B hi/lo fragments from fp32 R
    auto writeB = [&]() {
#pragma unroll
        for (int it = 0; it < 8; it++) {
            int f = tid + it * NTH;
            int q = f >> 8, nt = (f >> 5) & 7, l = f & 31;
            int ttt = l & 3, ggg = l >> 2;
            int col = nt * 8 + ggg, r0 = q * 16 + 2 * ttt;
            float v00 = R[r0 * RSTR + col],       v01 = R[(r0 + 1) * RSTR + col];
            float v10 = R[(r0 + 8) * RSTR + col], v11 = R[(r0 + 9) * RSTR + col];
            __nv_bfloat16 h00 = __float2bfloat16(v00), h01 = __float2bfloat16(v01);
            __nv_bfloat16 h10 = __float2bfloat16(v10), h11 = __float2bfloat16(v11);
            int o = q * 512 + nt * 64 + l * 2;
            BH[o]     = pkbf(h00, h01);
            BH[o + 1] = pkbf(h10, h11);
            BL[o]     = pkbf(__float2bfloat16(v00 - __bfloat162float(h00)),
                             __float2bfloat16(v01 - __bfloat162float(h01)));
            BL[o + 1] = pkbf(__float2bfloat16(v10 - __bfloat162float(h10)),
                             __float2bfloat16(v11 - __bfloat162float(h11)));
        }
    };
    auto readout = [&](int ts) {
        int b = tid & 63, seg = tid >> 6;
        const float* wr = WroS + ts * 256 + seg * 32;
        float s = 0.f;
#pragma unroll
        for (int r = 0; r < 32; r++) s += R[(seg * 32 + r) * RSTR + b] * wr[r];
        red[seg * 64 + b] = s;
        __syncthreads();
        if (tid < 64) {
            float a = broS[ts];
#pragma unroll
            for (int qq = 0; qq < 8; qq++) a += red[qq * 64 + tid];
            out[(size_t)(bBase + tid) * 10 + ts] = a;
        }
        __syncthreads();
    };

    writeB();
    __syncthreads();
    readout(0);

    float acc[4][2][4];
#pragma unroll
    for (int j = 0; j < 4; j++)
#pragma unroll
        for (int n = 0; n < 2; n++)
#pragma unroll
            for (int c = 0; c < 4; c++) acc[j][n][c] = 0.f;

    const float4* src = (const float4*)g_A;

    for (int s = 0; s < 9; s++) {
        {   // dW: tid = m*64+b (512 = 8*64)
            int m = tid >> 6, b = tid & 63;
            const float* ib = inc + (size_t)(bBase + b) * 80;
            dWs[tid] = (s == 0) ? (ib[m] + ib[8 + m]) : ib[(s + 1) * 8 + m];
        }
        // prime ping-pong
        float4 p0 = src[tid], p1 = src[512 + tid];
        ((float4*)AB)[tid] = p0; ((float4*)AB)[512 + tid] = p1;
        p0 = src[1024 + tid]; p1 = src[1536 + tid];
        __syncthreads();

        for (int ch = 0; ch < 144; ch++) {
            const u32* pbuf = AB + (ch & 1) * 4096;
            if (ch + 1 < 144) {
                float4* dst = (float4*)(AB + ((ch + 1) & 1) * 4096);
                dst[tid] = p0; dst[512 + tid] = p1;
            }
            if (ch + 2 < 144) {
                p0 = src[(ch + 2) * 1024 + tid];
                p1 = src[(ch + 2) * 1024 + 512 + tid];
            }
            int q = ch & 15;
            uint2 bh[2], bl[2];
#pragma unroll
            for (int n = 0; n < 2; n++) {
                int o = q * 512 + ((w >> 2) * 2 + n) * 64 + lane * 2;
                bh[n] = *(const uint2*)(BH + o);
                bl[n] = *(const uint2*)(BL + o);
            }
#pragma unroll
            for (int j = 0; j < 4; j++) {
                int mt = (w & 3) * 4 + j;
                uint4 ah = *(const uint4*)(pbuf + mt * 128 + lane * 4);
                uint4 al = *(const uint4*)(pbuf + 2048 + mt * 128 + lane * 4);
#pragma unroll
                for (int n = 0; n < 2; n++) {
                    mma16816(acc[j][n], ah, bh[n]);
                    mma16816(acc[j][n], ah, bl[n]);
                    mma16816(acc[j][n], al, bh[n]);
                }
            }
            if (q == 15) {          // epilogue for matrix m = ch>>4
                int m = ch >> 4;
#pragma unroll
                for (int j = 0; j < 4; j++) {
                    int i0 = rb + j * 16 + g;
                    float b0 = biasS[m * 256 + i0], b1 = biasS[m * 256 + i0 + 8];
#pragma unroll
                    for (int n = 0; n < 2; n++) {
                        int c0 = cbw + n * 8 + 2 * t;
                        float x0 = tanhf(acc[j][n][0] + b0);
                        float x1 = tanhf(acc[j][n][1] + b0);
                        float x2 = tanhf(acc[j][n][2] + b1);
                        float x3 = tanhf(acc[j][n][3] + b1);
                        float* r0p = &R[i0 * RSTR + c0];
                        float* r1p = &R[(i0 + 8) * RSTR + c0];
                        if (m == 0) {
                            r0p[0] += x0; r0p[1] += x1; r1p[0] += x2; r1p[1] += x3;
                        } else {
                            float d0 = dWs[(m - 1) * 64 + c0];
                            float d1 = dWs[(m - 1) * 64 + c0 + 1];
                            r0p[0] += x0 * d0; r0p[1] += x1 * d1;
                            r1p[0] += x2 * d0; r1p[1] += x3 * d1;
                        }
                        acc[j][n][0] = acc[j][n][1] = acc[j][n][2] = acc[j][n][3] = 0.f;
                    }
                }
            }
            __syncthreads();
        }
        writeB();
        __syncthreads();
        readout(s + 1);
    }
}

// ---------------- launch -----------------------------------------------------
extern "C" void kernel_launch(void* const* d_in, const int* in_sizes, int n_in,
                              void* d_out, int out_size) {
    const float* V    = (const float*)d_in[0];
    const float* inc  = (const float*)d_in[1];
    const float* W1   = (const float*)d_in[2];
    const float* b1v  = (const float*)d_in[3];
    const float* W2   = (const float*)d_in[4];
    const float* b2v  = (const float*)d_in[5];
    const float* rho1 = (const float*)d_in[6];
    const float* rho2 = (const float*)d_in[7];
    const float* rho3 = (const float*)d_in[8];
    const float* rho4 = (const float*)d_in[9];
    const float* B1m  = (const float*)d_in[10];
    const float* B2m  = (const float*)d_in[11];
    const float* lam1 = (const float*)d_in[12];
    const float* lam2 = (const float*)d_in[13];
    const float* Wro  = (const float*)d_in[14];
    const float* bro  = (const float*)d_in[15];
    float* out = (float*)d_out;

    const int nB = in_sizes[0] / 16;                  // 16384
    prep_kernel<<<(144 * 16 * 32 * 4 + 255) / 256, 256>>>(B1m, B2m, rho1, rho3);

    cudaFuncSetAttribute(sde_kernel, cudaFuncAttributeMaxDynamicSharedMemorySize, SM_TOT);
    sde_kernel<<<nB / BT, NTH, SM_TOT>>>(V, inc, W1, b1v, W2, b2v,
                                         rho2, rho4, lam1, lam2, Wro, bro, out);
}

// round 11
// speedup vs baseline: 4.7017x; 1.6280x over previous
#include <cuda_runtime.h>
#include <cuda_bf16.h>
#include <cstdint>
typedef unsigned int u32;

#define NTH  512
#define BT   64
// smem byte offsets
#define SO_BH   0          // B hi frags [16q][8n][32l][2] u32   32768
#define SO_BL   32768      // B lo frags                          32768
#define SO_BIAS 65536      // 9*256 fp32                           9216
#define SO_WRO  74752      // 10*256 fp32                         10240
#define SO_BRO  84992      // 10 fp32 (pad 64)                       64
#define SO_DW   85056      // 8*64 fp32                            2048
#define SO_RED  87104      // 16*64 fp32                           4096
#define SM_TOT  91200

// A fragments: [chunk 0..143][split hi/lo][mtile 16][lane 32][4 u32]
__device__ __align__(256) u32 g_A[144 * 4096];

__device__ __forceinline__ u32 pkbf(__nv_bfloat16 a, __nv_bfloat16 b) {
    return (u32)__bfloat16_as_ushort(a) | ((u32)__bfloat16_as_ushort(b) << 16);
}
__device__ __forceinline__ void mma16816(float c[4], const uint4& a, const uint2& b) {
    asm volatile("mma.sync.aligned.m16n8k16.row.col.f32.bf16.bf16.f32 "
        "{%0,%1,%2,%3}, {%4,%5,%6,%7}, {%8,%9}, {%0,%1,%2,%3};"
        : "+f"(c[0]), "+f"(c[1]), "+f"(c[2]), "+f"(c[3])
        : "r"(a.x), "r"(a.y), "r"(a.z), "r"(a.w), "r"(b.x), "r"(b.y));
}

// ---------------- prep: rho-fold + bf16 hi/lo split + fragment layout -------
__global__ void prep_kernel(const float* __restrict__ B1m, const float* __restrict__ B2m,
                            const float* __restrict__ r1, const float* __restrict__ r3) {
    int idx = blockIdx.x * 256 + threadIdx.x;
    if (idx >= 144 * 16 * 32 * 4) return;
    int r = idx & 3, l = (idx >> 2) & 31, mt = (idx >> 7) & 15, ch = idx >> 11;
    int m = ch >> 4, q = ch & 15;
    int gg = l >> 2, tt = l & 3;
    int i = mt * 16 + gg + ((r & 1) ? 8 : 0);
    int k = q * 16 + 2 * tt + ((r & 2) ? 8 : 0);
    float rho = (m == 0) ? r1[0] : r3[0];
    const float* Bs = (m == 0) ? (B1m + i * 256) : (B2m + (m - 1) * 65536 + i * 256);
    float v0 = rho * Bs[k], v1 = rho * Bs[k + 1];
    __nv_bfloat16 h0 = __float2bfloat16(v0), h1 = __float2bfloat16(v1);
    __nv_bfloat16 e0 = __float2bfloat16(v0 - __bfloat162float(h0));
    __nv_bfloat16 e1 = __float2bfloat16(v1 - __bfloat162float(h1));
    int base = ch * 4096 + mt * 128 + l * 4 + r;
    g_A[base]        = pkbf(h0, h1);
    g_A[base + 2048] = pkbf(e0, e1);
}

// ---------------- main kernel ------------------------------------------------
__global__ __launch_bounds__(NTH, 1)
void sde_kernel(const float* __restrict__ V, const float* __restrict__ inc,
                const float* __restrict__ W1, const float* __restrict__ b1v,
                const float* __restrict__ W2, const float* __restrict__ b2v,
                const float* __restrict__ rho2, const float* __restrict__ rho4,
                const float* __restrict__ lam1, const float* __restrict__ lam2,
                const float* __restrict__ Wro,  const float* __restrict__ bro,
                float* __restrict__ out) {
    extern __shared__ __align__(16) char sm[];
    u32*   BH    = (u32*)(sm + SO_BH);
    u32*   BL    = (u32*)(sm + SO_BL);
    float* biasS = (float*)(sm + SO_BIAS);
    float* WroS  = (float*)(sm + SO_WRO);
    float* broS  = (float*)(sm + SO_BRO);
    float* dWs   = (float*)(sm + SO_DW);
    float* red   = (float*)(sm + SO_RED);

    const int tid = threadIdx.x, lane = tid & 31, w = tid >> 5;
    const int g = lane >> 2, t = lane & 3;
    const int bBase = blockIdx.x * BT;
    const int iLo = w * 16 + g, iHi = iLo + 8;

    // prologue: biases (rho folded), readout weights
    {
        float r2 = rho2[0], r4 = rho4[0];
        for (int e = tid; e < 2304; e += NTH) {
            int m = e >> 8, i = e & 255;
            biasS[e] = (m == 0) ? r2 * lam1[i] : r4 * lam2[(m - 1) * 256 + i];
        }
        for (int e = tid; e < 2560; e += NTH) WroS[e] = Wro[e];
        if (tid < 10) broS[tid] = bro[tid];
    }
    // hT[j][b] = tanh(V W1^T + b1), staged in BH region
    float* hT = (float*)(sm + SO_BH);
    for (int e = tid; e < 2048; e += NTH) {
        int j = e & 31, b = e >> 5;
        const float* vb = V + (size_t)(bBase + b) * 16;
        const float* ww = W1 + j * 16;
        float s = b1v[j];
#pragma unroll
        for (int u = 0; u < 16; u++) s += vb[u] * ww[u];
        hT[j * 64 + b] = tanhf(s);
    }
    __syncthreads();

    // R0 in regs: R[n][{(iLo,cLo),(iLo,cHi),(iHi,cLo),(iHi,cHi)}], cLo=n*8+2t
    float R[8][4];
#pragma unroll
    for (int n = 0; n < 8; n++) R[n][0] = R[n][1] = R[n][2] = R[n][3] = 0.f;
    for (int j = 0; j < 32; j++) {
        float w2l = W2[iLo * 32 + j], w2h = W2[iHi * 32 + j];
#pragma unroll
        for (int n = 0; n < 8; n++) {
            float2 hv = *(const float2*)&hT[j * 64 + n * 8 + 2 * t];
            R[n][0] += hv.x * w2l; R[n][1] += hv.y * w2l;
            R[n][2] += hv.x * w2h; R[n][3] += hv.y * w2h;
        }
    }
    {
        float b2l = b2v[iLo], b2h = b2v[iHi];
#pragma unroll
        for (int n = 0; n < 8; n++) {
            R[n][0] += b2l; R[n][1] += b2l; R[n][2] += b2h; R[n][3] += b2h;
        }
    }
    __syncthreads();                 // hT region free (becomes BH)

    auto readout = [&](int ts) {
        float wl = WroS[ts * 256 + iLo], wh = WroS[ts * 256 + iHi];
        float pc[16];
#pragma unroll
        for (int n = 0; n < 8; n++) {
            pc[2 * n]     = R[n][0] * wl + R[n][2] * wh;
            pc[2 * n + 1] = R[n][1] * wl + R[n][3] * wh;
        }
#pragma unroll
        for (int k = 0; k < 16; k++) {
            pc[k] += __shfl_xor_sync(0xFFFFFFFFu, pc[k], 4);
            pc[k] += __shfl_xor_sync(0xFFFFFFFFu, pc[k], 8);
            pc[k] += __shfl_xor_sync(0xFFFFFFFFu, pc[k], 16);
        }
        if (lane < 4) {
#pragma unroll
            for (int n = 0; n < 8; n++) {
                red[w * 64 + n * 8 + 2 * lane]     = pc[2 * n];
                red[w * 64 + n * 8 + 2 * lane + 1] = pc[2 * n + 1];
            }
        }
        __syncthreads();
        if (tid < 64) {
            float a = broS[ts];
#pragma unroll
            for (int ww = 0; ww < 16; ww++) a += red[ww * 64 + tid];
            out[(size_t)(bBase + tid) * 10 + ts] = a;
        }
    };

    auto writeB = [&]() {
#pragma unroll
        for (int n = 0; n < 8; n++) {
            float v0 = R[n][0], v1 = R[n][1], v2 = R[n][2], v3 = R[n][3];
            __nv_bfloat16 h0 = __float2bfloat16(v0), h1 = __float2bfloat16(v1);
            __nv_bfloat16 h2 = __float2bfloat16(v2), h3 = __float2bfloat16(v3);
            u32 Ph01 = pkbf(h0, h1), Ph23 = pkbf(h2, h3);
            u32 Pl01 = pkbf(__float2bfloat16(v0 - __bfloat162float(h0)),
                            __float2bfloat16(v1 - __bfloat162float(h1)));
            u32 Pl23 = pkbf(__float2bfloat16(v2 - __bfloat162float(h2)),
                            __float2bfloat16(v3 - __bfloat162float(h3)));
            u32 Rh01 = __shfl_xor_sync(0xFFFFFFFFu, Ph01, 4);
            u32 Rh23 = __shfl_xor_sync(0xFFFFFFFFu, Ph23, 4);
            u32 Rl01 = __shfl_xor_sync(0xFFFFFFFFu, Pl01, 4);
            u32 Rl23 = __shfl_xor_sync(0xFFFFFFFFu, Pl23, 4);
            int a  = g >> 1;
            int iA = w * 512 + n * 64 + (2 * t * 4 + a) * 2;        // cLo, rows pair
            int iB = w * 512 + n * 64 + ((2 * t + 1) * 4 + a) * 2;  // cHi
            if ((g & 1) == 0) {   // even row: low half is own
                BH[iA]     = __byte_perm(Ph01, Rh01, 0x5410);
                BH[iB]     = __byte_perm(Ph01, Rh01, 0x7632);
                BH[iA + 1] = __byte_perm(Ph23, Rh23, 0x5410);
                BH[iB + 1] = __byte_perm(Ph23, Rh23, 0x7632);
            } else {              // odd row: own is high half; write lo split
                BL[iA]     = __byte_perm(Rl01, Pl01, 0x5410);
                BL[iB]     = __byte_perm(Rl01, Pl01, 0x7632);
                BL[iA + 1] = __byte_perm(Rl23, Pl23, 0x5410);
                BL[iB + 1] = __byte_perm(Rl23, Pl23, 0x7632);
            }
        }
    };

    readout(0);
    __syncthreads();
    writeB();

    const uint4* gA4 = (const uint4*)g_A;
    const int aoff = w * 32 + lane;
    const uint2* BH2 = (const uint2*)BH;
    const uint2* BL2 = (const uint2*)BL;

    for (int s = 0; s < 9; s++) {
        {   // dW for this step
            int m = tid >> 6, b = tid & 63;
            const float* ib = inc + (size_t)(bBase + b) * 80;
            dWs[tid] = (s == 0) ? (ib[m] + ib[8 + m]) : ib[(s + 1) * 8 + m];
        }
        __syncthreads();            // dW + B frags visible to all

        uint4 pah0 = gA4[aoff],        pal0 = gA4[512 + aoff];
        uint4 pah1 = gA4[1024 + aoff], pal1 = gA4[1536 + aoff];
        float acc[8][4];
#pragma unroll
        for (int n = 0; n < 8; n++) acc[n][0] = acc[n][1] = acc[n][2] = acc[n][3] = 0.f;

        auto chunk = [&](int ch, uint4& pah, uint4& pal) {
            uint4 ah = pah, al = pal;
            if (ch + 2 < 144) {
                int o = (ch + 2) * 1024 + aoff;
                pah = gA4[o]; pal = gA4[o + 512];
            }
            int q = ch & 15;
            uint2 bb[8];
            const uint2* bp = BH2 + q * 256 + lane;
#pragma unroll
            for (int n = 0; n < 8; n++) bb[n] = bp[n * 32];
#pragma unroll
            for (int n = 0; n < 8; n++) mma16816(acc[n], ah, bb[n]);
#pragma unroll
            for (int n = 0; n < 8; n++) mma16816(acc[n], al, bb[n]);
            bp = BL2 + q * 256 + lane;
#pragma unroll
            for (int n = 0; n < 8; n++) bb[n] = bp[n * 32];
#pragma unroll
            for (int n = 0; n < 8; n++) mma16816(acc[n], ah, bb[n]);
            if (q == 15) {          // epilogue: matrix m = ch>>4
                int m = ch >> 4;
                float bLo = biasS[m * 256 + iLo], bHi = biasS[m * 256 + iHi];
                if (m == 0) {
#pragma unroll
                    for (int n = 0; n < 8; n++) {
                        R[n][0] += tanhf(acc[n][0] + bLo);
                        R[n][1] += tanhf(acc[n][1] + bLo);
                        R[n][2] += tanhf(acc[n][2] + bHi);
                        R[n][3] += tanhf(acc[n][3] + bHi);
                        acc[n][0] = acc[n][1] = acc[n][2] = acc[n][3] = 0.f;
                    }
                } else {
#pragma unroll
                    for (int n = 0; n < 8; n++) {
                        float2 dw = *(const float2*)&dWs[(m - 1) * 64 + n * 8 + 2 * t];
                        R[n][0] += tanhf(acc[n][0] + bLo) * dw.x;
                        R[n][1] += tanhf(acc[n][1] + bLo) * dw.y;
                        R[n][2] += tanhf(acc[n][2] + bHi) * dw.x;
                        R[n][3] += tanhf(acc[n][3] + bHi) * dw.y;
                        acc[n][0] = acc[n][1] = acc[n][2] = acc[n][3] = 0.f;
                    }
                }
            }
        };

#pragma unroll 1
        for (int ch = 0; ch < 144; ch += 2) {
            chunk(ch,     pah0, pal0);
            chunk(ch + 1, pah1, pal1);
        }

        readout(s + 1);
        __syncthreads();            // all B-frag reads + red reads done
        if (s < 8) writeB();
    }
}

// ---------------- launch -----------------------------------------------------
extern "C" void kernel_launch(void* const* d_in, const int* in_sizes, int n_in,
                              void* d_out, int out_size) {
    const float* V    = (const float*)d_in[0];
    const float* inc  = (const float*)d_in[1];
    const float* W1   = (const float*)d_in[2];
    const float* b1v  = (const float*)d_in[3];
    const float* W2   = (const float*)d_in[4];
    const float* b2v  = (const float*)d_in[5];
    const float* rho1 = (const float*)d_in[6];
    const float* rho2 = (const float*)d_in[7];
    const float* rho3 = (const float*)d_in[8];
    const float* rho4 = (const float*)d_in[9];
    const float* B1m  = (const float*)d_in[10];
    const float* B2m  = (const float*)d_in[11];
    const float* lam1 = (const float*)d_in[12];
    const float* lam2 = (const float*)d_in[13];
    const float* Wro  = (const float*)d_in[14];
    const float* bro  = (const float*)d_in[15];
    float* out = (float*)d_out;

    const int nB = in_sizes[0] / 16;                  // 16384
    prep_kernel<<<(144 * 16 * 32 * 4 + 255) / 256, 256>>>(B1m, B2m, rho1, rho3);

    cudaFuncSetAttribute(sde_kernel, cudaFuncAttributeMaxDynamicSharedMemorySize, SM_TOT);
    sde_kernel<<<nB / BT, NTH, SM_TOT>>>(V, inc, W1, b1v, W2, b2v,
                                         rho2, rho4, lam1, lam2, Wro, bro, out);
}

// round 12
// speedup vs baseline: 6.3250x; 1.3453x over previous
#include <cuda_runtime.h>
#include <cuda_fp16.h>
#include <cstdint>
typedef unsigned int u32;

#define NTH  512
#define BT   64
// smem byte offsets
#define SO_BH   0          // B fp16 frags [16q][8n][32l][2] u32  32768
#define SO_BIAS 32768      // 9*256 fp32                           9216
#define SO_WRO  41984      // 10*256 fp32                         10240
#define SO_BRO  52224      // 10 fp32 (pad 64)                       64
#define SO_DW   52288      // 8*64 fp32                            2048
#define SO_RED  54336      // 16*64 fp32                           4096
#define SM_TOT  58432

// A fragments (fp16): [chunk 0..143][split hi/lo][mtile 16][lane 32][4 u32]
__device__ __align__(256) u32 g_A[144 * 4096];

__device__ __forceinline__ u32 pkhf(float a, float b) {
    __half2 h = __floats2half2_rn(a, b);
    return *(u32*)&h;
}
__device__ __forceinline__ void mma16816(float c[4], const uint4& a, const uint2& b) {
    asm volatile("mma.sync.aligned.m16n8k16.row.col.f32.f16.f16.f32 "
        "{%0,%1,%2,%3}, {%4,%5,%6,%7}, {%8,%9}, {%0,%1,%2,%3};"
        : "+f"(c[0]), "+f"(c[1]), "+f"(c[2]), "+f"(c[3])
        : "r"(a.x), "r"(a.y), "r"(a.z), "r"(a.w), "r"(b.x), "r"(b.y));
}

// ---------------- prep: rho-fold + fp16 hi/lo split + fragment layout -------
__global__ void prep_kernel(const float* __restrict__ B1m, const float* __restrict__ B2m,
                            const float* __restrict__ r1, const float* __restrict__ r3) {
    int idx = blockIdx.x * 256 + threadIdx.x;
    if (idx >= 144 * 16 * 32 * 4) return;
    int r = idx & 3, l = (idx >> 2) & 31, mt = (idx >> 7) & 15, ch = idx >> 11;
    int m = ch >> 4, q = ch & 15;
    int gg = l >> 2, tt = l & 3;
    int i = mt * 16 + gg + ((r & 1) ? 8 : 0);
    int k = q * 16 + 2 * tt + ((r & 2) ? 8 : 0);
    float rho = (m == 0) ? r1[0] : r3[0];
    const float* Bs = (m == 0) ? (B1m + i * 256) : (B2m + (m - 1) * 65536 + i * 256);
    float v0 = rho * Bs[k], v1 = rho * Bs[k + 1];
    __half h0 = __float2half_rn(v0), h1 = __float2half_rn(v1);
    float e0 = v0 - __half2float(h0), e1 = v1 - __half2float(h1);
    int base = ch * 4096 + mt * 128 + l * 4 + r;
    g_A[base]        = ((u32)__half_as_ushort(h0)) | ((u32)__half_as_ushort(h1) << 16);
    g_A[base + 2048] = pkhf(e0, e1);
}

// ---------------- main kernel ------------------------------------------------
__global__ __launch_bounds__(NTH, 1)
void sde_kernel(const float* __restrict__ V, const float* __restrict__ inc,
                const float* __restrict__ W1, const float* __restrict__ b1v,
                const float* __restrict__ W2, const float* __restrict__ b2v,
                const float* __restrict__ rho2, const float* __restrict__ rho4,
                const float* __restrict__ lam1, const float* __restrict__ lam2,
                const float* __restrict__ Wro,  const float* __restrict__ bro,
                float* __restrict__ out) {
    extern __shared__ __align__(16) char sm[];
    u32*   BH    = (u32*)(sm + SO_BH);
    float* biasS = (float*)(sm + SO_BIAS);
    float* WroS  = (float*)(sm + SO_WRO);
    float* broS  = (float*)(sm + SO_BRO);
    float* dWs   = (float*)(sm + SO_DW);
    float* red   = (float*)(sm + SO_RED);

    const int tid = threadIdx.x, lane = tid & 31, w = tid >> 5;
    const int g = lane >> 2, t = lane & 3;
    const int bBase = blockIdx.x * BT;
    const int iLo = w * 16 + g, iHi = iLo + 8;

    // prologue: biases (rho folded), readout weights
    {
        float r2 = rho2[0], r4 = rho4[0];
        for (int e = tid; e < 2304; e += NTH) {
            int m = e >> 8, i = e & 255;
            biasS[e] = (m == 0) ? r2 * lam1[i] : r4 * lam2[(m - 1) * 256 + i];
        }
        for (int e = tid; e < 2560; e += NTH) WroS[e] = Wro[e];
        if (tid < 10) broS[tid] = bro[tid];
    }
    // hT[j][b] = tanh(V W1^T + b1), staged in BH region
    float* hT = (float*)(sm + SO_BH);
    for (int e = tid; e < 2048; e += NTH) {
        int j = e & 31, b = e >> 5;
        const float* vb = V + (size_t)(bBase + b) * 16;
        const float* ww = W1 + j * 16;
        float s = b1v[j];
#pragma unroll
        for (int u = 0; u < 16; u++) s += vb[u] * ww[u];
        hT[j * 64 + b] = tanhf(s);
    }
    __syncthreads();

    // R0 in regs: R[n][{(iLo,cLo),(iLo,cHi),(iHi,cLo),(iHi,cHi)}], cLo=n*8+2t
    float R[8][4];
#pragma unroll
    for (int n = 0; n < 8; n++) R[n][0] = R[n][1] = R[n][2] = R[n][3] = 0.f;
    for (int j = 0; j < 32; j++) {
        float w2l = W2[iLo * 32 + j], w2h = W2[iHi * 32 + j];
#pragma unroll
        for (int n = 0; n < 8; n++) {
            float2 hv = *(const float2*)&hT[j * 64 + n * 8 + 2 * t];
            R[n][0] += hv.x * w2l; R[n][1] += hv.y * w2l;
            R[n][2] += hv.x * w2h; R[n][3] += hv.y * w2h;
        }
    }
    {
        float b2l = b2v[iLo], b2h = b2v[iHi];
#pragma unroll
        for (int n = 0; n < 8; n++) {
            R[n][0] += b2l; R[n][1] += b2l; R[n][2] += b2h; R[n][3] += b2h;
        }
    }
    __syncthreads();                 // hT region free (becomes BH)

    auto readout = [&](int ts) {
        float wl = WroS[ts * 256 + iLo], wh = WroS[ts * 256 + iHi];
        float pc[16];
#pragma unroll
        for (int n = 0; n < 8; n++) {
            pc[2 * n]     = R[n][0] * wl + R[n][2] * wh;
            pc[2 * n + 1] = R[n][1] * wl + R[n][3] * wh;
        }
#pragma unroll
        for (int k = 0; k < 16; k++) {
            pc[k] += __shfl_xor_sync(0xFFFFFFFFu, pc[k], 4);
            pc[k] += __shfl_xor_sync(0xFFFFFFFFu, pc[k], 8);
            pc[k] += __shfl_xor_sync(0xFFFFFFFFu, pc[k], 16);
        }
        if (lane < 4) {
#pragma unroll
            for (int n = 0; n < 8; n++) {
                red[w * 64 + n * 8 + 2 * lane]     = pc[2 * n];
                red[w * 64 + n * 8 + 2 * lane + 1] = pc[2 * n + 1];
            }
        }
        __syncthreads();
        if (tid < 64) {
            float a = broS[ts];
#pragma unroll
            for (int ww = 0; ww < 16; ww++) a += red[ww * 64 + tid];
            out[(size_t)(bBase + tid) * 10 + ts] = a;
        }
    };

    // pack fp16 B fragments from fp32 R (single buffer)
    auto writeB = [&]() {
#pragma unroll
        for (int n = 0; n < 8; n++) {
            u32 Ph01 = pkhf(R[n][0], R[n][1]);
            u32 Ph23 = pkhf(R[n][2], R[n][3]);
            u32 Rh01 = __shfl_xor_sync(0xFFFFFFFFu, Ph01, 4);
            u32 Rh23 = __shfl_xor_sync(0xFFFFFFFFu, Ph23, 4);
            if ((g & 1) == 0) {
                int a  = g >> 1;
                int iA = w * 512 + n * 64 + (2 * t * 4 + a) * 2;
                int iB = w * 512 + n * 64 + ((2 * t + 1) * 4 + a) * 2;
                BH[iA]     = __byte_perm(Ph01, Rh01, 0x5410);
                BH[iB]     = __byte_perm(Ph01, Rh01, 0x7632);
                BH[iA + 1] = __byte_perm(Ph23, Rh23, 0x5410);
                BH[iB + 1] = __byte_perm(Ph23, Rh23, 0x7632);
            }
        }
    };

    readout(0);
    __syncthreads();
    writeB();

    const uint4* gA4 = (const uint4*)g_A;
    const int aoff = w * 32 + lane;
    const uint2* BH2 = (const uint2*)BH;

    for (int s = 0; s < 9; s++) {
        {   // dW for this step
            int m = tid >> 6, b = tid & 63;
            const float* ib = inc + (size_t)(bBase + b) * 80;
            dWs[tid] = (s == 0) ? (ib[m] + ib[8 + m]) : ib[(s + 1) * 8 + m];
        }
        __syncthreads();            // dW + B frags visible to all

        uint4 pah0 = gA4[aoff],        pal0 = gA4[512 + aoff];
        uint4 pah1 = gA4[1024 + aoff], pal1 = gA4[1536 + aoff];
        float acc[8][4];
#pragma unroll
        for (int n = 0; n < 8; n++) acc[n][0] = acc[n][1] = acc[n][2] = acc[n][3] = 0.f;

        auto chunk = [&](int ch, uint4& pah, uint4& pal) {
            uint4 ah = pah, al = pal;
            if (ch + 2 < 144) {
                int o = (ch + 2) * 1024 + aoff;
                pah = gA4[o]; pal = gA4[o + 512];
            }
            int q = ch & 15;
            uint2 bb[8];
            const uint2* bp = BH2 + q * 256 + lane;
#pragma unroll
            for (int n = 0; n < 8; n++) bb[n] = bp[n * 32];
#pragma unroll
            for (int n = 0; n < 8; n++) mma16816(acc[n], ah, bb[n]);
#pragma unroll
            for (int n = 0; n < 8; n++) mma16816(acc[n], al, bb[n]);
            if (q == 15) {          // epilogue: matrix m = ch>>4
                int m = ch >> 4;
                float bLo = biasS[m * 256 + iLo], bHi = biasS[m * 256 + iHi];
                if (m == 0) {
#pragma unroll
                    for (int n = 0; n < 8; n++) {
                        R[n][0] += tanhf(acc[n][0] + bLo);
                        R[n][1] += tanhf(acc[n][1] + bLo);
                        R[n][2] += tanhf(acc[n][2] + bHi);
                        R[n][3] += tanhf(acc[n][3] + bHi);
                        acc[n][0] = acc[n][1] = acc[n][2] = acc[n][3] = 0.f;
                    }
                } else {
#pragma unroll
                    for (int n = 0; n < 8; n++) {
                        float2 dw = *(const float2*)&dWs[(m - 1) * 64 + n * 8 + 2 * t];
                        R[n][0] += tanhf(acc[n][0] + bLo) * dw.x;
                        R[n][1] += tanhf(acc[n][1] + bLo) * dw.y;
                        R[n][2] += tanhf(acc[n][2] + bHi) * dw.x;
                        R[n][3] += tanhf(acc[n][3] + bHi) * dw.y;
                        acc[n][0] = acc[n][1] = acc[n][2] = acc[n][3] = 0.f;
                    }
                }
            }
        };

#pragma unroll 1
        for (int ch = 0; ch < 144; ch += 2) {
            chunk(ch,     pah0, pal0);
            chunk(ch + 1, pah1, pal1);
        }

        readout(s + 1);
        __syncthreads();            // all B-frag reads + red reads done
        if (s < 8) writeB();
    }
}

// ---------------- launch -----------------------------------------------------
extern "C" void kernel_launch(void* const* d_in, const int* in_sizes, int n_in,
                              void* d_out, int out_size) {
    const float* V    = (const float*)d_in[0];
    const float* inc  = (const float*)d_in[1];
    const float* W1   = (const float*)d_in[2];
    const float* b1v  = (const float*)d_in[3];
    const float* W2   = (const float*)d_in[4];
    const float* b2v  = (const float*)d_in[5];
    const float* rho1 = (const float*)d_in[6];
    const float* rho2 = (const float*)d_in[7];
    const float* rho3 = (const float*)d_in[8];
    const float* rho4 = (const float*)d_in[9];
    const float* B1m  = (const float*)d_in[10];
    const float* B2m  = (const float*)d_in[11];
    const float* lam1 = (const float*)d_in[12];
    const float* lam2 = (const float*)d_in[13];
    const float* Wro  = (const float*)d_in[14];
    const float* bro  = (const float*)d_in[15];
    float* out = (float*)d_out;

    const int nB = in_sizes[0] / 16;                  // 16384
    prep_kernel<<<(144 * 16 * 32 * 4 + 255) / 256, 256>>>(B1m, B2m, rho1, rho3);

    cudaFuncSetAttribute(sde_kernel, cudaFuncAttributeMaxDynamicSharedMemorySize, SM_TOT);
    sde_kernel<<<nB / BT, NTH, SM_TOT>>>(V, inc, W1, b1v, W2, b2v,
                                         rho2, rho4, lam1, lam2, Wro, bro, out);
}